// round 17
// baseline (speedup 1.0000x reference)
#include <cuda_runtime.h>
typedef unsigned long long u64;
#define NB 16
#define NH 8

__device__ float g_A[NB * NH * 4 * 128];     // per (b,h,chunk): A+[64], A-[64]

__device__ __forceinline__ u64 pack2(float a, float b) {
    u64 r; asm("mov.b64 %0,{%1,%2};" : "=l"(r) : "f"(a), "f"(b)); return r;
}
__device__ __forceinline__ void fma2(u64& d, u64 a, u64 b) {
    asm("fma.rn.f32x2 %0,%1,%2,%0;" : "+l"(d) : "l"(a), "l"(b));
}
__device__ __forceinline__ float2 unpack2(u64 v) {
    float2 r; asm("mov.b64 {%0,%1},%2;" : "=f"(r.x), "=f"(r.y) : "l"(v)); return r;
}
__device__ __forceinline__ unsigned su32(const void* p) {
    unsigned r;
    asm("{.reg .u64 t; cvta.to.shared.u64 t,%1; cvt.u32.u64 %0,t;}" : "=r"(r) : "l"(p));
    return r;
}
#define CP16(d, s) asm volatile("cp.async.cg.shared.global [%0],[%1],16;" :: "r"(d), "l"(s))
#define CPC()      asm volatile("cp.async.commit_group;")

// ---------- k1: MLP (4 rows x 8 heads per warp) + fused partial A+/- ----------
// CTA = 32 rows of x = one 256-n chunk of m[b,h,:]. Writes only g_A.
__global__ void __launch_bounds__(256) k1_mlpA(const float* __restrict__ x,
                                               const float* __restrict__ w,
                                               const float* __restrict__ bias,
                                               const float* __restrict__ Q) {
    __shared__ __align__(16) float sw[8 * 1024];
    __shared__ float sb[8];
    __shared__ float sm_m[256];
    __shared__ float sp[4][64], sn[4][64];
    int tid = threadIdx.x;
    for (int i = tid; i < 2048; i += 256)
        ((float4*)sw)[i] = ((const float4*)w)[i];
    if (tid < 8) sb[tid] = bias[tid];
    __syncthreads();

    int warp = tid >> 5, lane = tid & 31;
    int row0 = blockIdx.x * 32 + warp * 4;
    const ulonglong2* x0 = (const ulonglong2*)(x + (long)row0 * 1024);

    u64 acc2[4][8];
#pragma unroll
    for (int r = 0; r < 4; ++r)
#pragma unroll
        for (int h = 0; h < 8; ++h) acc2[r][h] = 0ull;

#pragma unroll 2
    for (int j = 0; j < 8; ++j) {
        ulonglong2 xv[4];
#pragma unroll
        for (int r = 0; r < 4; ++r) xv[r] = x0[r * 256 + j * 32 + lane];
#pragma unroll
        for (int h = 0; h < 8; ++h) {
            const float* wr = &sw[h * 1024 + j * 128 + lane * 4];
            u64 w01 = *(const u64*)wr;
            u64 w23 = *(const u64*)(wr + 2);
#pragma unroll
            for (int r = 0; r < 4; ++r) {
                fma2(acc2[r][h], xv[r].x, w01);
                fma2(acc2[r][h], xv[r].y, w23);
            }
        }
    }

    float acc[4][8];
#pragma unroll
    for (int r = 0; r < 4; ++r)
#pragma unroll
        for (int h = 0; h < 8; ++h) {
            float2 p = unpack2(acc2[r][h]);
            acc[r][h] = p.x + p.y;
        }
#pragma unroll
    for (int r = 0; r < 4; ++r)
#pragma unroll
        for (int h = 0; h < 8; ++h)
#pragma unroll
            for (int off = 16; off > 0; off >>= 1)
                acc[r][h] += __shfl_xor_sync(0xffffffffu, acc[r][h], off);

    float sel = 0.f;
#pragma unroll
    for (int r = 0; r < 4; ++r)
#pragma unroll
        for (int h = 0; h < 8; ++h)
            if (lane == r * 8 + h) sel = acc[r][h];

    // lane l holds value for (row = row0 + (l>>3), c = l&7) -> n_loc = warp*32 + l
    sm_m[warp * 32 + lane] = tanhf(sel + sb[lane & 7]);
    __syncthreads();

    // fused partial A+/- over this CTA's 256-n chunk
    const int row0c = blockIdx.x * 32;
    const int b = row0c >> 10, j0 = row0c & 1023;
    const int h = j0 >> 7, chunk = (j0 & 127) >> 5;
    const int n0g = (j0 & 127) * 8;

    int e = tid & 63, q = tid >> 6;
    const float* qp = Q + ((long)(b * 1024 + n0g + q * 64) * 8 + h) * 64 + e;
    const float* mp = sm_m + q * 64;
    float ap = 0.f, an = 0.f;
#pragma unroll 8
    for (int n = 0; n < 64; ++n) {
        float m = mp[n];
        float qv = qp[(long)n * 512];
        ap += fmaxf(m, 0.f) * qv;
        an += fminf(m, 0.f) * qv;
    }
    sp[q][e] = ap; sn[q][e] = an;
    __syncthreads();
    long base = ((long)(b * 8 + h) * 4 + chunk) * 128;
    if (tid < 64)
        g_A[base + tid] = sp[0][tid] + sp[1][tid] + sp[2][tid] + sp[3][tid];
    else if (tid < 128) {
        int e2 = tid & 63;
        g_A[base + 64 + e2] = sn[0][e2] + sn[1][e2] + sn[2][e2] + sn[3][e2];
    }
}

// ---------- k3: fused u,t prologue + softmax + out = sum_s V P ----------
// dyn SM floats (19456 = 77824 B):
//   sV[2][64*68] @0..8704, sP[2][64*68] @8704..17408, u @17408, t @18432
__global__ void __launch_bounds__(256, 1) k3_attn(const float* __restrict__ K,
                                                  const float* __restrict__ V,
                                                  const float* __restrict__ sW,
                                                  float* __restrict__ out) {
    extern __shared__ __align__(16) float SM[];
    __shared__ float sA[128];
    const int h = blockIdx.x, b = blockIdx.y, tid = threadIdx.x;
    const unsigned smb = su32(SM);
    const int part = tid & 7, sl = tid >> 3;
    const int quarter = tid >> 6, eg = (tid >> 3) & 7, gg = tid & 7;
    const int warp = tid >> 5, lane = tid & 31;
    const int sg = lane >> 3, le = lane & 7;

    const float* Vb = V + ((long)b * 8192 + h) * 64;
    // issue V tile 0 immediately (overlaps with u,t compute)
#pragma unroll
    for (int i = 0; i < 4; ++i) {
        int idx = i * 256 + tid;
        int row = idx >> 4, col = (idx & 15) << 2;
        CP16(smb + (((unsigned)(row * 68 + col)) << 2), Vb + (long)row * 512 + col);
    }
    CPC();

    if (tid < 128) {
        const float* Ab = g_A + (long)(b * 8 + h) * 512 + tid;
        sA[tid] = Ab[0] + Ab[128] + Ab[256] + Ab[384];
    }
    float ra[8], rc[8];
#pragma unroll
    for (int j = 0; j < 8; ++j) {
        float w = sW[h * 64 + part * 8 + j];
        ra[j] = 0.125f * fmaxf(w, 0.f);
        rc[j] = 0.125f * fminf(w, 0.f);
    }
    __syncthreads();   // sA visible

    // u,t prologue: u[s] = K[s]·A+, t[s] = K[s]·A-  (1024 s, 32 per pass)
    {
        float rAp[8], rAn[8];
#pragma unroll
        for (int i = 0; i < 8; ++i) { rAp[i] = sA[le * 8 + i]; rAn[i] = sA[64 + le * 8 + i]; }
        const float* Kb = K + ((long)b * 8192 + h) * 64;
#pragma unroll 4
        for (int p = 0; p < 32; ++p) {
            int s = p * 32 + warp * 4 + sg;
            const float* kr = Kb + (long)s * 512 + le * 8;
            float4 k0 = *(const float4*)kr;
            float4 k1 = *(const float4*)(kr + 4);
            float kv[8] = {k0.x, k0.y, k0.z, k0.w, k1.x, k1.y, k1.z, k1.w};
            float u = 0.f, t = 0.f;
#pragma unroll
            for (int i = 0; i < 8; ++i) { u += kv[i] * rAp[i]; t += kv[i] * rAn[i]; }
#pragma unroll
            for (int off = 1; off < 8; off <<= 1) {
                u += __shfl_xor_sync(0xffffffffu, u, off);
                t += __shfl_xor_sync(0xffffffffu, t, off);
            }
            if (le == 0) { SM[17408 + s] = u; SM[18432 + s] = t; }
        }
    }
    __syncthreads();   // u,t visible

    u64 acc[32];
#pragma unroll
    for (int i = 0; i < 32; ++i) acc[i] = 0ull;

    for (int t = 0; t < 16; ++t) {
        int buf = t & 1;
        asm volatile("cp.async.wait_group 0;");

        // softmax for rows t*64+sl and +32 into sP[buf]
        float* pP = SM + 8704 + buf * 4352;
#pragma unroll
        for (int half = 0; half < 2; ++half) {
            int s = t * 64 + half * 32 + sl;
            float u = SM[17408 + s], tt = SM[18432 + s];
            float l[8], mx = -1e30f;
#pragma unroll
            for (int j = 0; j < 8; ++j) { l[j] = u * ra[j] + tt * rc[j]; mx = fmaxf(mx, l[j]); }
#pragma unroll
            for (int off = 1; off < 8; off <<= 1)
                mx = fmaxf(mx, __shfl_xor_sync(0xffffffffu, mx, off));
            float sum = 0.f;
#pragma unroll
            for (int j = 0; j < 8; ++j) { l[j] = __expf(l[j] - mx); sum += l[j]; }
#pragma unroll
            for (int off = 1; off < 8; off <<= 1)
                sum += __shfl_xor_sync(0xffffffffu, sum, off);
            float inv = __fdividef(1.f, sum);
            float* row = &pP[(half * 32 + sl) * 68 + part * 8];
            *(float4*)row       = make_float4(l[0] * inv, l[1] * inv, l[2] * inv, l[3] * inv);
            *(float4*)(row + 4) = make_float4(l[4] * inv, l[5] * inv, l[6] * inv, l[7] * inv);
        }
        __syncthreads();   // sV[buf] landed; sP[buf] visible; phaseB(t-1) done

        if (t + 1 < 16) {
            int s0 = (t + 1) * 64, nb = buf ^ 1;
#pragma unroll
            for (int i = 0; i < 4; ++i) {
                int idx = i * 256 + tid;
                int row = idx >> 4, col = (idx & 15) << 2;
                CP16(smb + (((unsigned)(nb * 4352 + row * 68 + col)) << 2),
                     Vb + (long)(s0 + row) * 512 + col);
            }
            CPC();
        } else {
            CPC();
        }

        // phase B: quarter covers full 64x64 over its 16 s
        const float* vb = SM + buf * 4352;
#pragma unroll
        for (int s16 = 0; s16 < 16; ++s16) {
            int sq = quarter * 16 + s16;
            float4 v0 = *(const float4*)&vb[sq * 68 + eg * 8];
            float4 v1 = *(const float4*)&vb[sq * 68 + eg * 8 + 4];
            ulonglong2 pA = *(const ulonglong2*)&pP[sq * 68 + gg * 8];
            ulonglong2 pB = *(const ulonglong2*)&pP[sq * 68 + gg * 8 + 4];
            float ve[8] = {v0.x, v0.y, v0.z, v0.w, v1.x, v1.y, v1.z, v1.w};
#pragma unroll
            for (int e = 0; e < 8; ++e) {
                u64 vv = pack2(ve[e], ve[e]);
                fma2(acc[e * 4 + 0], vv, pA.x);
                fma2(acc[e * 4 + 1], vv, pA.y);
                fma2(acc[e * 4 + 2], vv, pB.x);
                fma2(acc[e * 4 + 3], vv, pB.y);
            }
        }
        // no trailing barrier: BAR(t+1) orders phaseB(t) before sP[buf]/sV[buf] reuse
    }

    __syncthreads();
    u64* sred = (u64*)SM;
    if (tid >= 128) {
        int j = tid - 128;
#pragma unroll
        for (int i = 0; i < 32; ++i) sred[j * 32 + i] = acc[i];
    }
    __syncthreads();
    if (tid < 128) {
#pragma unroll
        for (int i = 0; i < 32; ++i) {
            float2 a = unpack2(acc[i]), c = unpack2(sred[tid * 32 + i]);
            acc[i] = pack2(a.x + c.x, a.y + c.y);
        }
    }
    __syncthreads();
    if (tid >= 64 && tid < 128) {
#pragma unroll
        for (int i = 0; i < 32; ++i) sred[(tid - 64) * 32 + i] = acc[i];
    }
    __syncthreads();
    if (tid < 64) {
#pragma unroll
        for (int i = 0; i < 32; ++i) {
            float2 a = unpack2(acc[i]), c = unpack2(sred[tid * 32 + i]);
            acc[i] = pack2(a.x + c.x, a.y + c.y);
        }
#pragma unroll
        for (int e = 0; e < 8; ++e) {
            long ob = ((long)(b * 64 + eg * 8 + e) * 8 + h) * 64 + gg * 8;
            float2 p0 = unpack2(acc[e * 4 + 0]), p1 = unpack2(acc[e * 4 + 1]);
            float2 p2 = unpack2(acc[e * 4 + 2]), p3 = unpack2(acc[e * 4 + 3]);
            *(float4*)&out[ob]     = make_float4(p0.x, p0.y, p1.x, p1.y);
            *(float4*)&out[ob + 4] = make_float4(p2.x, p2.y, p3.x, p3.y);
        }
    }
}

extern "C" void kernel_launch(void* const* d_in, const int* in_sizes, int n_in,
                              void* d_out, int out_size) {
    const float* q  = (const float*)d_in[0];
    const float* k  = (const float*)d_in[1];
    const float* v  = (const float*)d_in[2];
    const float* x  = (const float*)d_in[3];
    const float* mw = (const float*)d_in[4];
    const float* mb = (const float*)d_in[5];
    const float* sW = (const float*)d_in[6];
    (void)in_sizes; (void)n_in; (void)out_size;
    float* out = (float*)d_out;

    cudaFuncSetAttribute(k3_attn, cudaFuncAttributeMaxDynamicSharedMemorySize, 19456 * 4);

    k1_mlpA<<<512, 256>>>(x, mw, mb, q);
    k3_attn<<<dim3(NH, NB), 256, 19456 * 4>>>(k, v, sW, out);
}